// round 9
// baseline (speedup 1.0000x reference)
#include <cuda_runtime.h>

#define BDIM 256

typedef unsigned long long u64;

// Global scratch (no allocation allowed)
__device__ float g_flat[2048 * 162];
__device__ float g_h[2048 * 500];
__device__ float g_wbuf[6984];

// Duplicated weights in constant memory: each original weight w stored as (w, w).
// float4 element = (w_j, w_j, w_{j+1}, w_{j+1}).
// layout (float4 idx): [0,216) W1 9cf x 24 | [216,1296) W2 45cf x 24 | [1296,1746) W3 45cf x 10
__constant__ float4 c_w4d[1746];

// ---------------------------------------------------------------------------
// f32x2 packed helpers
// ---------------------------------------------------------------------------
__device__ __forceinline__ u64 pk(float lo, float hi) {
    u64 r; asm("mov.b64 %0, {%1, %2};" : "=l"(r) : "f"(lo), "f"(hi)); return r;
}
__device__ __forceinline__ float2 upk(u64 v) {
    float lo, hi; asm("mov.b64 {%0, %1}, %2;" : "=f"(lo), "=f"(hi) : "l"(v));
    return make_float2(lo, hi);
}
__device__ __forceinline__ u64 fma2(u64 a, u64 b, u64 c) {
    u64 d; asm("fma.rn.f32x2 %0, %1, %2, %3;" : "=l"(d) : "l"(a), "l"(b), "l"(c));
    return d;
}

// ---------------------------------------------------------------------------
// Prep kernel: interleave raw weights, duplicated (w,w), into g_wbuf.
// Original combined layout idx: [0,432) W1 [9cf][48] | [432,2592) W2 [45cf][48]
// | [2592,3492) W3 [45cf][20].  Duplicated: g_wbuf[2*idx] = g_wbuf[2*idx+1] = v.
// ---------------------------------------------------------------------------
__global__ void prep_weights_kernel(const float* __restrict__ bw1, const float* __restrict__ sw1,
                                    const float* __restrict__ bw2, const float* __restrict__ sw2,
                                    const float* __restrict__ bw3, const float* __restrict__ sw3)
{
    int tid = blockIdx.x * blockDim.x + threadIdx.x;
    for (int idx = tid; idx < 432; idx += gridDim.x * blockDim.x) {
        int cf = idx / 48, j = idx % 48;
        float v = 0.0f;
        if (j < 45) {
            int t = j / 5, o = j % 5;
            v = (cf == 0) ? bw1[o * 9 + t] : sw1[(o * 9 + t) * 8 + (cf - 1)];
        }
        g_wbuf[2 * idx] = v; g_wbuf[2 * idx + 1] = v;
    }
    for (int idx = tid; idx < 2160; idx += gridDim.x * blockDim.x) {
        int cf = idx / 48, j = idx % 48;
        float v = 0.0f;
        if (j < 45) {
            int c = cf / 9, f = cf % 9;
            int t = j / 5, o = j % 5;
            int kk = c * 9 + t;
            v = (f == 0) ? bw2[o * 45 + kk] : sw2[(o * 45 + kk) * 8 + (f - 1)];
        }
        int d = 432 + idx;
        g_wbuf[2 * d] = v; g_wbuf[2 * d + 1] = v;
    }
    for (int idx = tid; idx < 900; idx += gridDim.x * blockDim.x) {
        int cf = idx / 20, j = idx % 20;
        float v = 0.0f;
        if (j < 18) {
            int c = cf / 9, f = cf % 9;
            int t = j / 2, o = j % 2;
            int kk = c * 9 + t;
            v = (f == 0) ? bw3[o * 45 + kk] : sw3[(o * 45 + kk) * 8 + (f - 1)];
        }
        int d = 2592 + idx;
        g_wbuf[2 * d] = v; g_wbuf[2 * d + 1] = v;
    }
}

// ---------------------------------------------------------------------------
// packed phi: per-component silu + all 8 cubic B-spline bases (branchless).
// base[f*stride + p] holds float2 (img0, img1). knots t_i = -2.2 + 0.4*i.
// ---------------------------------------------------------------------------
__device__ __forceinline__ void spline4(float x, float* w, int* k)
{
    float s  = (x + 2.2f) * 2.5f;
    float kf = floorf(s);
    *k = (int)kf;
    float u  = s - kf;
    float u2 = u * u, u3 = u2 * u;
    float um = 1.0f - u;
    const float c6 = 1.0f / 6.0f;
    w[0] = um * um * um * c6;
    w[1] = (3.0f * u3 - 6.0f * u2 + 4.0f) * c6;
    w[2] = (-3.0f * u3 + 3.0f * u2 + 3.0f * u + 1.0f) * c6;
    w[3] = u3 * c6;
}

__device__ __forceinline__ void write_phi9_2(float2* base, int stride, int p, float2 x)
{
    float sa = __fdividef(x.x, 1.0f + __expf(-x.x));
    float sb = __fdividef(x.y, 1.0f + __expf(-x.y));
    base[p] = make_float2(sa, sb);

    float wa[4], wb[4]; int ka, kb;
    spline4(x.x, wa, &ka);
    spline4(x.y, wb, &kb);
    bool ina = (ka >= 0) && (ka <= 10);
    bool inb = (kb >= 0) && (kb <= 10);

#pragma unroll
    for (int i = 0; i < 8; ++i) {
        int da = i - (ka - 3), db = i - (kb - 3);
        float va = 0.0f, vb = 0.0f;
        va = (da == 0) ? wa[0] : va;
        va = (da == 1) ? wa[1] : va;
        va = (da == 2) ? wa[2] : va;
        va = (da == 3) ? wa[3] : va;
        vb = (db == 0) ? wb[0] : vb;
        vb = (db == 1) ? wb[1] : vb;
        vb = (db == 2) ? wb[2] : vb;
        vb = (db == 3) ? wb[3] : vb;
        base[(1 + i) * stride + p] = make_float2(ina ? va : 0.0f, inb ? vb : 0.0f);
    }
}

// ---------------------------------------------------------------------------
// Fused conv stack, 2 images per block packed as f32x2.
// dyn smem (float2): bufA2 7608 | aux2 845  -> 8453 float2 = 67,624 B
// ---------------------------------------------------------------------------
__global__ __launch_bounds__(BDIM, 2)
void conv_stack_kernel(const float* __restrict__ x)
{
    extern __shared__ __align__(16) float2 dsm[];
    float2* bufA2 = dsm;
    float2* aux2  = dsm + 7608;
    u64* bufAu = (u64*)bufA2;
    u64* auxu  = (u64*)aux2;

    const int tid  = threadIdx.x;
    const int img0 = 2 * blockIdx.x;
    const float* xin0 = x + img0 * 784;
    const float* xin1 = xin0 + 784;

    // ---- featurize input: feat1 [9][784] packed
    for (int p = tid; p < 784; p += BDIM)
        write_phi9_2(bufA2, 784, p, make_float2(xin0[p], xin1[p]));
    __syncthreads();

    // ---- conv1 (9 cf, 5 out) + 2x2 maxpool -> aux2 = p1 [5][169]
    if (tid < 169) {
        int py = tid / 13, px = tid % 13;
        u64 a0[5] = {0,0,0,0,0}, a1[5] = {0,0,0,0,0};
        u64 a2[5] = {0,0,0,0,0}, a3[5] = {0,0,0,0,0};
        for (int cf = 0; cf < 9; ++cf) {
            const float2* fp = bufA2 + cf * 784 + (2 * py) * 28 + 2 * px;
            u64 v[16];
#pragma unroll
            for (int r = 0; r < 4; ++r) {
                const float4* fp4 = (const float4*)(fp + r * 28);
                float4 q0 = fp4[0], q1 = fp4[1];
                v[r * 4 + 0] = pk(q0.x, q0.y);
                v[r * 4 + 1] = pk(q0.z, q0.w);
                v[r * 4 + 2] = pk(q1.x, q1.y);
                v[r * 4 + 3] = pk(q1.z, q1.w);
            }
            int qb = cf * 24;
#pragma unroll
            for (int q = 0; q < 24; ++q) {
                float4 t4 = c_w4d[qb + q];
                u64 wd[2] = { pk(t4.x, t4.y), pk(t4.z, t4.w) };
#pragma unroll
                for (int m = 0; m < 2; ++m) {
                    int j = 2 * q + m;
                    if (j < 45) {
                        int t = j / 5, o = j % 5, ty = t / 3, tx = t % 3;
                        u64 wj = wd[m];
                        a0[o] = fma2(wj, v[ty * 4 + tx],           a0[o]);
                        a1[o] = fma2(wj, v[ty * 4 + tx + 1],       a1[o]);
                        a2[o] = fma2(wj, v[(ty + 1) * 4 + tx],     a2[o]);
                        a3[o] = fma2(wj, v[(ty + 1) * 4 + tx + 1], a3[o]);
                    }
                }
            }
        }
#pragma unroll
        for (int o = 0; o < 5; ++o) {
            float2 r0 = upk(a0[o]), r1 = upk(a1[o]), r2 = upk(a2[o]), r3 = upk(a3[o]);
            aux2[o * 169 + tid] = make_float2(
                fmaxf(fmaxf(r0.x, r1.x), fmaxf(r2.x, r3.x)),
                fmaxf(fmaxf(r0.y, r1.y), fmaxf(r2.y, r3.y)));
        }
    }
    __syncthreads();

    // ---- featurize pooled: feat2 [45][169]
    for (int idx = tid; idx < 845; idx += BDIM) {
        int c = idx / 169, p = idx % 169;
        write_phi9_2(bufA2 + c * 9 * 169, 169, p, aux2[idx]);
    }
    __syncthreads();

    // ---- conv2 (45 cf, 5 out): 13x13 -> 11x11; point pair (t, t+61)
    if (tid < 61) {
        int pA = tid, pB = tid + 61;
        bool hasB = (pB < 121);
        int yA = pA / 11, xA = pA % 11;
        int yB = pB / 11, xB = pB % 11;
        u64 aA[5] = {0,0,0,0,0}, aB[5] = {0,0,0,0,0};
        for (int cf = 0; cf < 45; ++cf) {
            const u64* fA = bufAu + cf * 169 + yA * 13 + xA;
            const u64* fB = bufAu + cf * 169 + yB * 13 + xB;
            u64 vA[9], vB[9];
#pragma unroll
            for (int r = 0; r < 3; ++r)
#pragma unroll
                for (int c = 0; c < 3; ++c) {
                    vA[r * 3 + c] = fA[r * 13 + c];
                    vB[r * 3 + c] = fB[r * 13 + c];
                }
            int qb = 216 + cf * 24;
#pragma unroll
            for (int q = 0; q < 24; ++q) {
                float4 t4 = c_w4d[qb + q];
                u64 wd[2] = { pk(t4.x, t4.y), pk(t4.z, t4.w) };
#pragma unroll
                for (int m = 0; m < 2; ++m) {
                    int j = 2 * q + m;
                    if (j < 45) {
                        int t = j / 5, o = j % 5;
                        aA[o] = fma2(wd[m], vA[t], aA[o]);
                        aB[o] = fma2(wd[m], vB[t], aB[o]);
                    }
                }
            }
        }
#pragma unroll
        for (int o = 0; o < 5; ++o) {
            auxu[o * 121 + pA] = aA[o];
            if (hasB) auxu[o * 121 + pB] = aB[o];
        }
    }
    __syncthreads();

    // ---- featurize h2: feat3 [45][121]
    for (int idx = tid; idx < 605; idx += BDIM) {
        int c = idx / 121, p = idx % 121;
        write_phi9_2(bufA2 + c * 9 * 121, 121, p, aux2[idx]);
    }
    __syncthreads();

    // ---- conv3 (45 cf, 2 out): 11x11 -> 9x9; point pair (t, t+41)
    if (tid < 41) {
        int pA = tid, pB = tid + 41;
        bool hasB = (pB < 81);
        int yA = pA / 9, xA = pA % 9;
        int yB = pB / 9, xB = pB % 9;
        u64 aA[2] = {0, 0}, aB[2] = {0, 0};
        for (int cf = 0; cf < 45; ++cf) {
            const u64* fA = bufAu + cf * 121 + yA * 11 + xA;
            const u64* fB = bufAu + cf * 121 + yB * 11 + xB;
            u64 vA[9], vB[9];
#pragma unroll
            for (int r = 0; r < 3; ++r)
#pragma unroll
                for (int c = 0; c < 3; ++c) {
                    vA[r * 3 + c] = fA[r * 11 + c];
                    vB[r * 3 + c] = fB[r * 11 + c];
                }
            int qb = 1296 + cf * 10;
#pragma unroll
            for (int q = 0; q < 10; ++q) {
                float4 t4 = c_w4d[qb + q];
                u64 wd[2] = { pk(t4.x, t4.y), pk(t4.z, t4.w) };
#pragma unroll
                for (int m = 0; m < 2; ++m) {
                    int j = 2 * q + m;
                    if (j < 18) {
                        int t = j / 2, o = j % 2;
                        aA[o] = fma2(wd[m], vA[t], aA[o]);
                        aB[o] = fma2(wd[m], vB[t], aB[o]);
                    }
                }
            }
        }
        float* o0 = g_flat + img0 * 162;
        float* o1 = o0 + 162;
        float2 rA0 = upk(aA[0]), rA1 = upk(aA[1]);
        o0[pA] = rA0.x; o0[81 + pA] = rA1.x;
        o1[pA] = rA0.y; o1[81 + pA] = rA1.y;
        if (hasB) {
            float2 rB0 = upk(aB[0]), rB1 = upk(aB[1]);
            o0[pB] = rB0.x; o0[81 + pB] = rB1.x;
            o1[pB] = rB0.y; o1[81 + pB] = rB1.y;
        }
    }
}

// ---------------------------------------------------------------------------
// FC1: h[B,500] = relu(flat[B,162] @ w1^T + b1);  w1: [500,162]
// ---------------------------------------------------------------------------
__global__ __launch_bounds__(256)
void fc1_kernel(const float* __restrict__ w1, const float* __restrict__ b1, int B)
{
    __shared__ float Bs[64 * 163];
    const int tid = threadIdx.x;
    const int row0 = blockIdx.x * 64;
    const int col0 = blockIdx.y * 64;

    for (int idx = tid; idx < 64 * 162; idx += 256) {
        int n = idx / 162, k = idx % 162;
        int col = col0 + n;
        Bs[n * 163 + k] = (col < 500) ? w1[col * 162 + k] : 0.0f;
    }
    __syncthreads();

    const int i = tid >> 4, j = tid & 15;
    float acc[4][4];
#pragma unroll
    for (int r = 0; r < 4; ++r)
#pragma unroll
        for (int c = 0; c < 4; ++c) acc[r][c] = 0.0f;

    const float* Ap = g_flat + (row0 + i * 4) * 162;
    for (int k = 0; k < 162; ++k) {
        float a0 = Ap[k], a1 = Ap[162 + k], a2 = Ap[324 + k], a3 = Ap[486 + k];
        float b[4];
#pragma unroll
        for (int c = 0; c < 4; ++c) b[c] = Bs[(j + 16 * c) * 163 + k];
#pragma unroll
        for (int c = 0; c < 4; ++c) {
            acc[0][c] = fmaf(a0, b[c], acc[0][c]);
            acc[1][c] = fmaf(a1, b[c], acc[1][c]);
            acc[2][c] = fmaf(a2, b[c], acc[2][c]);
            acc[3][c] = fmaf(a3, b[c], acc[3][c]);
        }
    }
#pragma unroll
    for (int r = 0; r < 4; ++r)
#pragma unroll
        for (int c = 0; c < 4; ++c) {
            int col = col0 + j + 16 * c;
            if (col < 500) {
                float v = acc[r][c] + b1[col];
                g_h[(row0 + i * 4 + r) * 500 + col] = fmaxf(v, 0.0f);
            }
        }
}

// ---------------------------------------------------------------------------
// FC2: out[B,10] = h[B,500] @ w2^T + b2. One warp per row, 8 rows/block.
// ---------------------------------------------------------------------------
__global__ __launch_bounds__(256)
void fc2_kernel(const float* __restrict__ w2, const float* __restrict__ b2,
                float* __restrict__ out, int B)
{
    const int tid = threadIdx.x;
    const int warp = tid >> 5, lane = tid & 31;
    const int row = blockIdx.x * 8 + warp;

    float acc[10];
#pragma unroll
    for (int o = 0; o < 10; ++o) acc[o] = 0.0f;

    const float4* hv = (const float4*)(g_h + row * 500);
    const float4* wv = (const float4*)w2;           // [10][125] float4
#pragma unroll
    for (int c = 0; c < 4; ++c) {
        int i = lane + 32 * c;
        if (i < 125) {
            float4 hh = hv[i];
#pragma unroll
            for (int o = 0; o < 10; ++o) {
                float4 ww = __ldg(wv + o * 125 + i);
                acc[o] = fmaf(hh.x, ww.x, acc[o]);
                acc[o] = fmaf(hh.y, ww.y, acc[o]);
                acc[o] = fmaf(hh.z, ww.z, acc[o]);
                acc[o] = fmaf(hh.w, ww.w, acc[o]);
            }
        }
    }
#pragma unroll
    for (int o = 0; o < 10; ++o) {
#pragma unroll
        for (int off = 16; off > 0; off >>= 1)
            acc[o] += __shfl_down_sync(0xffffffffu, acc[o], off);
    }
    if (lane == 0) {
#pragma unroll
        for (int o = 0; o < 10; ++o)
            out[row * 10 + o] = acc[o] + b2[o];
    }
}

// ---------------------------------------------------------------------------
extern "C" void kernel_launch(void* const* d_in, const int* in_sizes, int n_in,
                              void* d_out, int out_size)
{
    const float* x   = (const float*)d_in[0];
    const float* bw1 = (const float*)d_in[1];
    const float* sw1 = (const float*)d_in[2];
    const float* bw2 = (const float*)d_in[3];
    const float* sw2 = (const float*)d_in[4];
    const float* bw3 = (const float*)d_in[5];
    const float* sw3 = (const float*)d_in[6];
    const float* w1  = (const float*)d_in[7];
    const float* b1  = (const float*)d_in[8];
    const float* w2  = (const float*)d_in[9];
    const float* b2  = (const float*)d_in[10];
    float* out = (float*)d_out;

    int B = in_sizes[0] / 784;
    const int SMEM_BYTES = 8453 * 8;    // 67,624 B dynamic smem

    static bool attr_set = false;
    if (!attr_set) {
        cudaFuncSetAttribute(conv_stack_kernel,
                             cudaFuncAttributeMaxDynamicSharedMemorySize, SMEM_BYTES);
        attr_set = true;
    }

    prep_weights_kernel<<<4, 256>>>(bw1, sw1, bw2, sw2, bw3, sw3);

    void* wbuf_ptr = nullptr;
    cudaGetSymbolAddress(&wbuf_ptr, g_wbuf);
    cudaMemcpyToSymbolAsync(c_w4d, wbuf_ptr, 6984 * sizeof(float), 0,
                            cudaMemcpyDeviceToDevice, 0);

    conv_stack_kernel<<<B / 2, BDIM, SMEM_BYTES>>>(x);
    fc1_kernel<<<dim3(B / 64, 8), 256>>>(w1, b1, B);
    fc2_kernel<<<B / 8, 256>>>(w2, b2, out, B);
}